// round 15
// baseline (speedup 1.0000x reference)
#include <cuda_runtime.h>
#include <cuda_bf16.h>
#include <cuda_fp16.h>
#include <math.h>
#include <stdint.h>

#define BB 4
#define NN 2048
#define NF 256
#define NH 8
#define DD 64
#define C1 512
#define NO 128

__device__ float  g_h1[BB*NN*C1];
__device__ float  g_h2[BB*NN*NO];
__device__ float2 g_ef1[BB*NN*NH];
__device__ float2 g_ef2[BB*NN*NH];
__device__ float2 g_ef1o[BB*NN];
__device__ float2 g_ef2o[BB*NN];
__device__ __half g_h1T[BB*C1*NN];
__device__ __half g_h2T[BB*NO*NN];
__device__ uint32_t g_adjp[BB*NN*(NN/32)];
__device__ __nv_bfloat16 g_xh[BB*NN*NF],  g_xl[BB*NN*NF];
__device__ __nv_bfloat16 g_WhT_h[C1*NF],  g_WhT_l[C1*NF];
__device__ __nv_bfloat16 g_WoT_h[NO*C1],  g_WoT_l[NO*C1];
__device__ __nv_bfloat16 g_z1h[BB*NN*C1], g_z1l[BB*NN*C1];

// ---------------- helpers ----------------
__device__ __forceinline__ uint32_t smem_to_u32(const void* p) {
    uint32_t a;
    asm("{ .reg .u64 t; cvta.to.shared.u64 t, %1; cvt.u32.u64 %0, t; }" : "=r"(a) : "l"(p));
    return a;
}
#define LDM_X4(r, addr) \
    asm volatile("ldmatrix.sync.aligned.m8n8.x4.shared.b16 {%0,%1,%2,%3}, [%4];" \
        : "=r"((r)[0]), "=r"((r)[1]), "=r"((r)[2]), "=r"((r)[3]) : "r"(addr))
#define MMA_BF16(d, a, b0, b1) \
    asm volatile("mma.sync.aligned.m16n8k16.row.col.f32.bf16.bf16.f32 " \
        "{%0,%1,%2,%3}, {%4,%5,%6,%7}, {%8,%9}, {%0,%1,%2,%3};" \
        : "+f"((d)[0]), "+f"((d)[1]), "+f"((d)[2]), "+f"((d)[3]) \
        : "r"((a)[0]), "r"((a)[1]), "r"((a)[2]), "r"((a)[3]), "r"(b0), "r"(b1))
#define MMA_F16(d, a, b0, b1) \
    asm volatile("mma.sync.aligned.m16n8k16.row.col.f32.f16.f16.f32 " \
        "{%0,%1,%2,%3}, {%4,%5,%6,%7}, {%8,%9}, {%0,%1,%2,%3};" \
        : "+f"((d)[0]), "+f"((d)[1]), "+f"((d)[2]), "+f"((d)[3]) \
        : "r"((a)[0]), "r"((a)[1]), "r"((a)[2]), "r"((a)[3]), "r"(b0), "r"(b1))
#define CP_A16(smem, gptr) \
    asm volatile("cp.async.ca.shared.global [%0], [%1], 16;" :: "r"(smem), "l"(gptr))
#define CP_A8(smem, gptr) \
    asm volatile("cp.async.ca.shared.global [%0], [%1], 8;" :: "r"(smem), "l"(gptr))
#define CP_COMMIT() asm volatile("cp.async.commit_group;" ::: "memory")
#define CP_WAIT0()  asm volatile("cp.async.wait_group 0;" ::: "memory")

__device__ __forceinline__ uint32_t pack_bf16(float e0, float e1) {
    uint32_t r;
    asm("cvt.rn.satfinite.bf16x2.f32 %0, %1, %2;" : "=r"(r) : "f"(e1), "f"(e0));
    return r;
}
__device__ __forceinline__ uint32_t pack_f16(float e0, float e1) {
    uint32_t r;
    asm("cvt.rn.f16x2.f32 %0, %1, %2;" : "=r"(r) : "f"(e1), "f"(e0));
    return r;
}
__device__ __forceinline__ void split_pair(float w0, float w1, uint32_t& hi, uint32_t& lo) {
    hi = pack_bf16(w0, w1);
    float r0 = w0 - __uint_as_float(hi << 16);
    float r1 = w1 - __uint_as_float(hi & 0xFFFF0000u);
    lo = pack_bf16(r0, r1);
}
__device__ __forceinline__ float pair_sum_h(uint32_t p) {
    __half2 h = *reinterpret_cast<__half2*>(&p);
    float2 f = __half22float2(h);
    return f.x + f.y;
}

// ---------------- prep ----------------
__global__ __launch_bounds__(256) void pack_adj_kernel(const int* __restrict__ adj) {
    const int lane = threadIdx.x & 31, warp = threadIdx.x >> 5;
    const int row = blockIdx.x * 8 + warp;
    const size_t base = (size_t)row * NN;
    uint32_t w0 = 0, w1 = 0;
    #pragma unroll 8
    for (int g = 0; g < 64; ++g) {
        uint32_t bits = __ballot_sync(0xFFFFFFFFu, adj[base + g*32 + lane] > 0);
        if (g < 32) { if (lane == g) w0 = bits; }
        else        { if (lane == g - 32) w1 = bits; }
    }
    g_adjp[(size_t)row*64 + lane] = w0;
    g_adjp[(size_t)row*64 + 32 + lane] = w1;
}
__global__ __launch_bounds__(256) void split_x_kernel(const float* __restrict__ x) {
    size_t i = (size_t)blockIdx.x * 256 + threadIdx.x;
    float2 v = ((const float2*)x)[i];
    uint32_t hi, lo; split_pair(v.x, v.y, hi, lo);
    ((uint32_t*)g_xh)[i] = hi;
    ((uint32_t*)g_xl)[i] = lo;
}
__global__ __launch_bounds__(128) void transWh_kernel(const float* __restrict__ Wh) {
    const int n = blockIdx.x, t = threadIdx.x;
    const int h = n >> 6, o = n & 63;
    float a = Wh[(size_t)h*NF*DD + (size_t)(2*t)*DD + o];
    float b = Wh[(size_t)h*NF*DD + (size_t)(2*t+1)*DD + o];
    uint32_t hi, lo; split_pair(a, b, hi, lo);
    ((uint32_t*)g_WhT_h)[n*(NF/2) + t] = hi;
    ((uint32_t*)g_WhT_l)[n*(NF/2) + t] = lo;
}
__global__ __launch_bounds__(256) void transWo_kernel(const float* __restrict__ Wo) {
    const int n = blockIdx.x, t = threadIdx.x;
    float a = Wo[(size_t)(2*t)*NO + n];
    float b = Wo[(size_t)(2*t+1)*NO + n];
    uint32_t hi, lo; split_pair(a, b, hi, lo);
    ((uint32_t*)g_WoT_h)[n*(C1/2) + t] = hi;
    ((uint32_t*)g_WoT_l)[n*(C1/2) + t] = lo;
}

// ---------------- GEMM via mma.sync (3-pass bf16 split) ----------------
__device__ __forceinline__ void gemm_mma_body(
    const __nv_bfloat16* __restrict__ Ah, const __nv_bfloat16* __restrict__ Al,
    const __nv_bfloat16* __restrict__ BTh, const __nv_bfloat16* __restrict__ BTl,
    float* __restrict__ Out, int K, int Ncols, int nkt, char* dsm) {
    __nv_bfloat16* sAh = (__nv_bfloat16*)dsm;
    __nv_bfloat16* sAl = sAh + 64*72;
    __nv_bfloat16* sBh = sAl + 64*72;
    __nv_bfloat16* sBl = sBh + 128*72;
    const int tid = threadIdx.x, warp = tid >> 5, lane = tid & 31;
    const int mi = warp >> 1, ni = warp & 1;
    const int m0 = blockIdx.y * 64, n0 = blockIdx.x * 128;
    const uint32_t sAhA = smem_to_u32(sAh), sAlA = smem_to_u32(sAl);
    const uint32_t sBhA = smem_to_u32(sBh), sBlA = smem_to_u32(sBl);
    const int rq = lane >> 2, cq = lane & 3;

    float acc[4][2][4] = {};
    for (int kt = 0; kt < nkt; ++kt) {
        const int k0 = kt * 64;
        __syncthreads();
        #pragma unroll
        for (int rr = 0; rr < 2; ++rr) {
            int idx = tid + rr*256;
            int row = idx >> 3, ch = idx & 7;
            size_t so = (size_t)(m0 + row)*K + k0 + ch*8;
            *(uint4*)(sAh + row*72 + ch*8) = *(const uint4*)(Ah + so);
            *(uint4*)(sAl + row*72 + ch*8) = *(const uint4*)(Al + so);
        }
        #pragma unroll
        for (int rr = 0; rr < 4; ++rr) {
            int idx = tid + rr*256;
            int row = idx >> 3, ch = idx & 7;
            size_t so = (size_t)(n0 + row)*K + k0 + ch*8;
            *(uint4*)(sBh + row*72 + ch*8) = *(const uint4*)(BTh + so);
            *(uint4*)(sBl + row*72 + ch*8) = *(const uint4*)(BTl + so);
        }
        __syncthreads();
        #pragma unroll
        for (int ks = 0; ks < 4; ++ks) {
            const int jb = ks * 16;
            uint32_t ah4[4], al4[4];
            uint32_t aoff = (uint32_t)(((mi*16 + (lane & 15))*72 + jb + (lane >> 4)*8) * 2);
            LDM_X4(ah4, sAhA + aoff);
            LDM_X4(al4, sAlA + aoff);
            #pragma unroll
            for (int np = 0; np < 4; ++np) {
                uint32_t boff = (uint32_t)(((ni*64 + np*16 + (lane & 15))*72 + jb + (lane >> 4)*8) * 2);
                uint32_t bh4[4], bl4[4];
                LDM_X4(bh4, sBhA + boff);
                LDM_X4(bl4, sBlA + boff);
                MMA_BF16(acc[np][0], ah4, bh4[0], bh4[2]);
                MMA_BF16(acc[np][1], ah4, bh4[1], bh4[3]);
                MMA_BF16(acc[np][0], ah4, bl4[0], bl4[2]);
                MMA_BF16(acc[np][1], ah4, bl4[1], bl4[3]);
                MMA_BF16(acc[np][0], al4, bh4[0], bh4[2]);
                MMA_BF16(acc[np][1], al4, bh4[1], bh4[3]);
            }
        }
    }
    const int r0 = m0 + mi*16 + rq, r1 = r0 + 8;
    #pragma unroll
    for (int np = 0; np < 4; ++np)
        #pragma unroll
        for (int n8 = 0; n8 < 2; ++n8) {
            const int c = n0 + ni*64 + np*16 + n8*8 + cq*2;
            const float* a = acc[np][n8];
            *(float2*)&Out[(size_t)r0*Ncols + c] = make_float2(a[0], a[1]);
            *(float2*)&Out[(size_t)r1*Ncols + c] = make_float2(a[2], a[3]);
        }
}
__global__ __launch_bounds__(256) void gemm1_mma_kernel() {
    extern __shared__ __align__(16) char dsm[];
    gemm_mma_body(g_xh, g_xl, g_WhT_h, g_WhT_l, g_h1, NF, C1, NF/64, dsm);
}
__global__ __launch_bounds__(256) void gemm2_mma_kernel() {
    extern __shared__ __align__(16) char dsm[];
    gemm_mma_body(g_z1h, g_z1l, g_WoT_h, g_WoT_l, g_h2, C1, NO, C1/64, dsm);
}

// ---------------- scores ----------------
__global__ __launch_bounds__(256) void scores1_kernel(const float* __restrict__ ah) {
    const int n = blockIdx.x, b = blockIdx.y;
    const int w = threadIdx.x >> 5, lane = threadIdx.x & 31;
    const size_t row = (size_t)b * NN + n;
    const float* hrow = &g_h1[row * C1 + w * DD];
    float v0 = hrow[lane], v1 = hrow[lane + 32];
    const float* a = &ah[w * 2 * DD];
    float s1 = v0 * a[lane] + v1 * a[lane + 32];
    float s2 = v0 * a[DD + lane] + v1 * a[DD + lane + 32];
    #pragma unroll
    for (int s = 16; s; s >>= 1) {
        s1 += __shfl_down_sync(0xFFFFFFFFu, s1, s);
        s2 += __shfl_down_sync(0xFFFFFFFFu, s2, s);
    }
    if (lane == 0) {
        g_ef1[row * NH + w] = make_float2(expf(s1), expf(0.1f * s1));
        g_ef2[row * NH + w] = make_float2(expf(s2), expf(0.1f * s2));
    }
}
__global__ __launch_bounds__(128) void scores2_kernel(const float* __restrict__ ao) {
    __shared__ float s1s[128], s2s[128];
    const int n = blockIdx.x, b = blockIdx.y;
    const size_t row = (size_t)b * NN + n;
    const int t = threadIdx.x;
    float v = g_h2[row * NO + t];
    s1s[t] = v * ao[t];
    s2s[t] = v * ao[NO + t];
    __syncthreads();
    for (int s = 64; s; s >>= 1) {
        if (t < s) { s1s[t] += s1s[t + s]; s2s[t] += s2s[t + s]; }
        __syncthreads();
    }
    if (t == 0) {
        g_ef1o[row] = make_float2(expf(s1s[0]), expf(0.1f * s1s[0]));
        g_ef2o[row] = make_float2(expf(s2s[0]), expf(0.1f * s2s[0]));
    }
}

// ---------------- transpose -> fp16 ----------------
__device__ __forceinline__ void trans_f16(const float* __restrict__ src,
                                          __half* __restrict__ dst, int C) {
    __shared__ float tsm[32][33];
    const int lane = threadIdx.x & 31, ty = threadIdx.x >> 5;
    const int n0 = blockIdx.x * 32, c0 = blockIdx.y * 32, b = blockIdx.z;
    #pragma unroll
    for (int r = 0; r < 4; ++r)
        tsm[ty + r*8][lane] = src[((size_t)b*NN + n0 + ty + r*8)*C + c0 + lane];
    __syncthreads();
    #pragma unroll
    for (int r = 0; r < 4; ++r) {
        float v = tsm[lane][ty + r*8];
        dst[((size_t)b*C + c0 + ty + r*8)*NN + n0 + lane] = __float2half(v);
    }
}
__global__ __launch_bounds__(256) void trans1_kernel() { trans_f16(g_h1, g_h1T, C1); }
__global__ __launch_bounds__(256) void trans2_kernel() { trans_f16(g_h2, g_h2T, NO); }

// ---------------- agg1: fp16 mma.sync, cp.async double-buffered ----------------
__global__ __launch_bounds__(256) void agg1_mma_kernel(const float* __restrict__ bh) {
    extern __shared__ __align__(16) char dsm[];
    // layout: B0 (64*72 h), B1, ef0 (64 f2), ef1 (64 f2)
    const int BBYTES = 64*72*2;
    __half* sB = (__half*)dsm;
    float2* sef = (float2*)(dsm + 2*BBYTES);

    const int tid = threadIdx.x, warp = tid >> 5, lane = tid & 31;
    const int head = blockIdx.x, i0 = blockIdx.y * 128, b = blockIdx.z;
    const int iw = i0 + warp * 16;
    const uint32_t sBA = smem_to_u32(sB);
    const uint32_t sefA = smem_to_u32(sef);
    const int rq = lane >> 2, cq = lane & 3;

    float2 u[2];
    u[0] = g_ef1[((size_t)b*NN + iw + rq)*NH + head];
    u[1] = g_ef1[((size_t)b*NN + iw + rq + 8)*NH + head];
    float lac[2] = {};
    float acc[4][2][4] = {};

    // stage tile jt into buffer bufi
    auto stage = [&](int jt, int bufi) {
        const int j0 = jt * 64;
        const uint32_t sb = sBA + bufi * BBYTES;
        #pragma unroll
        for (int rr = 0; rr < 2; ++rr) {
            int idx = tid + rr*256;
            int row = idx >> 3, ch = idx & 7;
            size_t so = ((size_t)(b*C1 + head*DD + row))*NN + j0 + ch*8;
            CP_A16(sb + (uint32_t)(row*72 + ch*8)*2, g_h1T + so);
        }
        if (tid < 64)
            CP_A8(sefA + (uint32_t)(bufi*64 + tid)*8,
                  &g_ef2[((size_t)b*NN + j0 + tid)*NH + head]);
        CP_COMMIT();
    };

    stage(0, 0);
    uint2 mc[2];
    mc[0] = *(const uint2*)&g_adjp[((size_t)b*NN + iw + rq)*64];
    mc[1] = *(const uint2*)&g_adjp[((size_t)b*NN + iw + rq + 8)*64];

    for (int jt = 0; jt < 32; ++jt) {
        CP_WAIT0();
        __syncthreads();
        if (jt + 1 < 32) stage(jt + 1, (jt + 1) & 1);
        uint2 mn[2];
        if (jt + 1 < 32) {
            const int jn = (jt + 1) * 64;
            mn[0] = *(const uint2*)&g_adjp[((size_t)b*NN + iw + rq)*64 + (jn >> 5)];
            mn[1] = *(const uint2*)&g_adjp[((size_t)b*NN + iw + rq + 8)*64 + (jn >> 5)];
        }
        const uint32_t sb = sBA + (jt & 1) * BBYTES;
        const float2* ef = sef + (jt & 1) * 64;

        #pragma unroll
        for (int ks = 0; ks < 4; ++ks) {
            const int jb = ks * 16;
            float4 va = *(const float4*)&ef[jb + 2*cq];
            float4 vb = *(const float4*)&ef[jb + 2*cq + 8];
            uint32_t ahi[4];
            #pragma unroll
            for (int h = 0; h < 2; ++h) {
                uint32_t mw = (ks < 2) ? mc[h].x : mc[h].y;
                const int sh = (ks & 1)*16 + 2*cq;
                const float2 uu = u[h];
                float w0 = ((mw >> sh) & 1u)     ? fmaxf(uu.x*va.x, uu.y*va.y) : 0.0f;
                float w1 = ((mw >> (sh+1)) & 1u) ? fmaxf(uu.x*va.z, uu.y*va.w) : 0.0f;
                float w2 = ((mw >> (sh+8)) & 1u) ? fmaxf(uu.x*vb.x, uu.y*vb.y) : 0.0f;
                float w3 = ((mw >> (sh+9)) & 1u) ? fmaxf(uu.x*vb.z, uu.y*vb.w) : 0.0f;
                uint32_t hA = pack_f16(w0, w1);
                uint32_t hB = pack_f16(w2, w3);
                lac[h] += pair_sum_h(hA) + pair_sum_h(hB);
                ahi[h] = hA;  ahi[h+2] = hB;
            }
            #pragma unroll
            for (int np = 0; np < 4; ++np) {
                uint32_t boff = sb + (uint32_t)(((np*16 + (lane & 15))*72 + jb + (lane >> 4)*8) * 2);
                uint32_t b4[4];
                LDM_X4(b4, boff);
                MMA_F16(acc[np][0], ahi, b4[0], b4[2]);
                MMA_F16(acc[np][1], ahi, b4[1], b4[3]);
            }
        }
        mc[0] = mn[0]; mc[1] = mn[1];
    }
    #pragma unroll
    for (int h = 0; h < 2; ++h) {
        lac[h] += __shfl_xor_sync(0xFFFFFFFFu, lac[h], 1);
        lac[h] += __shfl_xor_sync(0xFFFFFFFFu, lac[h], 2);
    }
    const float inv0 = 1.0f / lac[0], inv1 = 1.0f / lac[1];
    const int r0 = iw + rq, r1 = r0 + 8;
    #pragma unroll
    for (int np = 0; np < 4; ++np)
        #pragma unroll
        for (int n8 = 0; n8 < 2; ++n8) {
            const int c = np*16 + n8*8 + cq*2;
            const float bb0 = bh[head*DD + c], bb1 = bh[head*DD + c + 1];
            const float* a = acc[np][n8];
            float z00 = a[0]*inv0 + bb0, z01 = a[1]*inv0 + bb1;
            float z10 = a[2]*inv1 + bb0, z11 = a[3]*inv1 + bb1;
            z00 = (z00 > 0.0f) ? z00 : expm1f(z00);
            z01 = (z01 > 0.0f) ? z01 : expm1f(z01);
            z10 = (z10 > 0.0f) ? z10 : expm1f(z10);
            z11 = (z11 > 0.0f) ? z11 : expm1f(z11);
            uint32_t zh, zl;
            split_pair(z00, z01, zh, zl);
            *(uint32_t*)&g_z1h[((size_t)b*NN + r0)*C1 + head*DD + c] = zh;
            *(uint32_t*)&g_z1l[((size_t)b*NN + r0)*C1 + head*DD + c] = zl;
            split_pair(z10, z11, zh, zl);
            *(uint32_t*)&g_z1h[((size_t)b*NN + r1)*C1 + head*DD + c] = zh;
            *(uint32_t*)&g_z1l[((size_t)b*NN + r1)*C1 + head*DD + c] = zl;
        }
}

// ---------------- agg2: fp16 mma.sync, N=128, cp.async double-buffered ----------------
__global__ __launch_bounds__(128) void agg2_mma_kernel(const float* __restrict__ bo,
                                                       float* __restrict__ out) {
    extern __shared__ __align__(16) char dsm[];
    const int BBYTES = 128*72*2;
    __half* sB = (__half*)dsm;
    float2* sef = (float2*)(dsm + 2*BBYTES);

    const int tid = threadIdx.x, warp = tid >> 5, lane = tid & 31;
    const int i0 = blockIdx.x * 32, b = blockIdx.y;
    const int mi = warp >> 1, ni = warp & 1;
    const int iw = i0 + mi * 16;
    const uint32_t sBA = smem_to_u32(sB);
    const uint32_t sefA = smem_to_u32(sef);
    const int rq = lane >> 2, cq = lane & 3;

    float2 u[2];
    u[0] = g_ef1o[(size_t)b*NN + iw + rq];
    u[1] = g_ef1o[(size_t)b*NN + iw + rq + 8];
    float lac[2] = {};
    float acc[4][2][4] = {};

    auto stage = [&](int jt, int bufi) {
        const int j0 = jt * 64;
        const uint32_t sb = sBA + bufi * BBYTES;
        #pragma unroll
        for (int rr = 0; rr < 8; ++rr) {
            int idx = tid + rr*128;
            int row = idx >> 3, ch = idx & 7;
            size_t so = ((size_t)(b*NO + row))*NN + j0 + ch*8;
            CP_A16(sb + (uint32_t)(row*72 + ch*8)*2, g_h2T + so);
        }
        if (tid < 64)
            CP_A8(sefA + (uint32_t)(bufi*64 + tid)*8, &g_ef2o[(size_t)b*NN + j0 + tid]);
        CP_COMMIT();
    };

    stage(0, 0);
    uint2 mc[2];
    mc[0] = *(const uint2*)&g_adjp[((size_t)b*NN + iw + rq)*64];
    mc[1] = *(const uint2*)&g_adjp[((size_t)b*NN + iw + rq + 8)*64];

    for (int jt = 0; jt < 32; ++jt) {
        CP_WAIT0();
        __syncthreads();
        if (jt + 1 < 32) stage(jt + 1, (jt + 1) & 1);
        uint2 mn[2];
        if (jt + 1 < 32) {
            const int jn = (jt + 1) * 64;
            mn[0] = *(const uint2*)&g_adjp[((size_t)b*NN + iw + rq)*64 + (jn >> 5)];
            mn[1] = *(const uint2*)&g_adjp[((size_t)b*NN + iw + rq + 8)*64 + (jn >> 5)];
        }
        const uint32_t sb = sBA + (jt & 1) * BBYTES;
        const float2* ef = sef + (jt & 1) * 64;

        #pragma unroll
        for (int ks = 0; ks < 4; ++ks) {
            const int jb = ks * 16;
            float4 va = *(const float4*)&ef[jb + 2*cq];
            float4 vb = *(const float4*)&ef[jb + 2*cq + 8];
            uint32_t ahi[4];
            #pragma unroll
            for (int h = 0; h < 2; ++h) {
                uint32_t mw = (ks < 2) ? mc[h].x : mc[h].y;
                const int sh = (ks & 1)*16 + 2*cq;
                const float2 uu = u[h];
                float w0 = ((mw >> sh) & 1u)     ? fmaxf(uu.x*va.x, uu.y*va.y) : 0.0f;
                float w1 = ((mw >> (sh+1)) & 1u) ? fmaxf(uu.x*va.z, uu.y*va.w) : 0.0f;
                float w2 = ((mw >> (sh+8)) & 1u) ? fmaxf(uu.x*vb.x, uu.y*vb.y) : 0.0f;
                float w3 = ((mw >> (sh+9)) & 1u) ? fmaxf(uu.x*vb.z, uu.y*vb.w) : 0.0f;
                uint32_t hA = pack_f16(w0, w1);
                uint32_t hB = pack_f16(w2, w3);
                lac[h] += pair_sum_h(hA) + pair_sum_h(hB);
                ahi[h] = hA;  ahi[h+2] = hB;
            }
            #pragma unroll
            for (int np = 0; np < 4; ++np) {
                uint32_t boff = sb + (uint32_t)(((ni*64 + np*16 + (lane & 15))*72 + jb + (lane >> 4)*8) * 2);
                uint32_t b4[4];
                LDM_X4(b4, boff);
                MMA_F16(acc[np][0], ahi, b4[0], b4[2]);
                MMA_F16(acc[np][1], ahi, b4[1], b4[3]);
            }
        }
        mc[0] = mn[0]; mc[1] = mn[1];
    }
    #pragma unroll
    for (int h = 0; h < 2; ++h) {
        lac[h] += __shfl_xor_sync(0xFFFFFFFFu, lac[h], 1);
        lac[h] += __shfl_xor_sync(0xFFFFFFFFu, lac[h], 2);
    }
    const float inv0 = 1.0f / lac[0], inv1 = 1.0f / lac[1];
    const int r0 = iw + rq, r1 = r0 + 8;
    #pragma unroll
    for (int np = 0; np < 4; ++np)
        #pragma unroll
        for (int n8 = 0; n8 < 2; ++n8) {
            const int c = ni*64 + np*16 + n8*8 + cq*2;
            const float bb0 = bo[c], bb1 = bo[c + 1];
            const float* a = acc[np][n8];
            float z00 = fmaxf(a[0]*inv0 + bb0, 0.0f);
            float z01 = fmaxf(a[1]*inv0 + bb1, 0.0f);
            float z10 = fmaxf(a[2]*inv1 + bb0, 0.0f);
            float z11 = fmaxf(a[3]*inv1 + bb1, 0.0f);
            *(float2*)&out[((size_t)b*NN + r0)*NO + c] = make_float2(z00, z01);
            *(float2*)&out[((size_t)b*NN + r1)*NO + c] = make_float2(z10, z11);
        }
}

// ---------------------------------------------------------------------------
extern "C" void kernel_launch(void* const* d_in, const int* in_sizes, int n_in,
                              void* d_out, int out_size) {
    const float* x   = (const float*)d_in[0];
    const int*   adj = (const int*)  d_in[1];
    const float* Wh  = (const float*)d_in[2];
    const float* ah  = (const float*)d_in[3];
    const float* bh  = (const float*)d_in[4];
    const float* Wo  = (const float*)d_in[5];
    const float* ao  = (const float*)d_in[6];
    const float* bo  = (const float*)d_in[7];
    float* out = (float*)d_out;

    const int smem_gemm = (64 + 64 + 128 + 128) * 72 * 2;   // 55296
    const int smem1 = 2*64*72*2 + 2*64*8;    // 19456
    const int smem2 = 2*128*72*2 + 2*64*8;   // 37888
    cudaFuncSetAttribute(gemm1_mma_kernel, cudaFuncAttributeMaxDynamicSharedMemorySize, smem_gemm);
    cudaFuncSetAttribute(gemm2_mma_kernel, cudaFuncAttributeMaxDynamicSharedMemorySize, smem_gemm);
    cudaFuncSetAttribute(agg1_mma_kernel, cudaFuncAttributeMaxDynamicSharedMemorySize, smem1);
    cudaFuncSetAttribute(agg2_mma_kernel, cudaFuncAttributeMaxDynamicSharedMemorySize, smem2);

    pack_adj_kernel<<<(BB*NN)/8, 256>>>(adj);
    split_x_kernel<<<(BB*NN*NF/2)/256, 256>>>(x);
    transWh_kernel<<<C1, 128>>>(Wh);
    transWo_kernel<<<NO, 256>>>(Wo);

    gemm1_mma_kernel<<<dim3(C1/128, (BB*NN)/64), 256, smem_gemm>>>();
    scores1_kernel<<<dim3(NN, BB), 256>>>(ah);
    trans1_kernel<<<dim3(NN / 32, C1 / 32, BB), 256>>>();
    agg1_mma_kernel<<<dim3(NH, NN / 128, BB), 256, smem1>>>(bh);

    gemm2_mma_kernel<<<dim3(NO/128, (BB*NN)/64), 256, smem_gemm>>>();
    scores2_kernel<<<dim3(NN, BB), 128>>>(ao);
    trans2_kernel<<<dim3(NN / 32, NO / 32, BB), 256>>>();
    agg2_mma_kernel<<<dim3(NN / 32, BB), 128, smem2>>>(bo, out);
}

// round 16
// speedup vs baseline: 1.5172x; 1.5172x over previous
#include <cuda_runtime.h>
#include <cuda_bf16.h>
#include <cuda_fp16.h>
#include <math.h>
#include <stdint.h>

#define BB 4
#define NN 2048
#define NF 256
#define NH 8
#define DD 64
#define C1 512
#define NO 128

__device__ float  g_h1[BB*NN*C1];
__device__ float  g_h2[BB*NN*NO];
__device__ float2 g_ef1[BB*NN*NH];
__device__ float2 g_ef2[BB*NN*NH];
__device__ float2 g_ef1o[BB*NN];
__device__ float2 g_ef2o[BB*NN];
__device__ __half g_h1T[BB*C1*NN];
__device__ __half g_h2T[BB*NO*NN];
__device__ uint32_t g_adjp[BB*NN*(NN/32)];
__device__ __nv_bfloat16 g_xh[BB*NN*NF],  g_xl[BB*NN*NF];
__device__ __nv_bfloat16 g_WhT_h[C1*NF],  g_WhT_l[C1*NF];
__device__ __nv_bfloat16 g_WoT_h[NO*C1],  g_WoT_l[NO*C1];
__device__ __nv_bfloat16 g_z1h[BB*NN*C1], g_z1l[BB*NN*C1];

// ---------------- helpers ----------------
__device__ __forceinline__ uint32_t smem_to_u32(const void* p) {
    uint32_t a;
    asm("{ .reg .u64 t; cvta.to.shared.u64 t, %1; cvt.u32.u64 %0, t; }" : "=r"(a) : "l"(p));
    return a;
}
#define LDM_X4(r, addr) \
    asm volatile("ldmatrix.sync.aligned.m8n8.x4.shared.b16 {%0,%1,%2,%3}, [%4];" \
        : "=r"((r)[0]), "=r"((r)[1]), "=r"((r)[2]), "=r"((r)[3]) : "r"(addr))
#define MMA_BF16(d, a, b0, b1) \
    asm volatile("mma.sync.aligned.m16n8k16.row.col.f32.bf16.bf16.f32 " \
        "{%0,%1,%2,%3}, {%4,%5,%6,%7}, {%8,%9}, {%0,%1,%2,%3};" \
        : "+f"((d)[0]), "+f"((d)[1]), "+f"((d)[2]), "+f"((d)[3]) \
        : "r"((a)[0]), "r"((a)[1]), "r"((a)[2]), "r"((a)[3]), "r"(b0), "r"(b1))
#define MMA_F16(d, a, b0, b1) \
    asm volatile("mma.sync.aligned.m16n8k16.row.col.f32.f16.f16.f32 " \
        "{%0,%1,%2,%3}, {%4,%5,%6,%7}, {%8,%9}, {%0,%1,%2,%3};" \
        : "+f"((d)[0]), "+f"((d)[1]), "+f"((d)[2]), "+f"((d)[3]) \
        : "r"((a)[0]), "r"((a)[1]), "r"((a)[2]), "r"((a)[3]), "r"(b0), "r"(b1))

__device__ __forceinline__ uint32_t pack_bf16(float e0, float e1) {
    uint32_t r;
    asm("cvt.rn.satfinite.bf16x2.f32 %0, %1, %2;" : "=r"(r) : "f"(e1), "f"(e0));
    return r;
}
__device__ __forceinline__ uint32_t pack_f16(float e0, float e1) {
    uint32_t r;
    asm("cvt.rn.f16x2.f32 %0, %1, %2;" : "=r"(r) : "f"(e1), "f"(e0));
    return r;
}
__device__ __forceinline__ void split_pair(float w0, float w1, uint32_t& hi, uint32_t& lo) {
    hi = pack_bf16(w0, w1);
    float r0 = w0 - __uint_as_float(hi << 16);
    float r1 = w1 - __uint_as_float(hi & 0xFFFF0000u);
    lo = pack_bf16(r0, r1);
}
__device__ __forceinline__ float pair_sum_h(uint32_t p) {
    __half2 h = *reinterpret_cast<__half2*>(&p);
    float2 f = __half22float2(h);
    return f.x + f.y;
}

// ---------------- prep ----------------
__global__ __launch_bounds__(256) void pack_adj_kernel(const int* __restrict__ adj) {
    const int lane = threadIdx.x & 31, warp = threadIdx.x >> 5;
    const int row = blockIdx.x * 8 + warp;
    const size_t base = (size_t)row * NN;
    uint32_t w0 = 0, w1 = 0;
    #pragma unroll 8
    for (int g = 0; g < 64; ++g) {
        uint32_t bits = __ballot_sync(0xFFFFFFFFu, adj[base + g*32 + lane] > 0);
        if (g < 32) { if (lane == g) w0 = bits; }
        else        { if (lane == g - 32) w1 = bits; }
    }
    g_adjp[(size_t)row*64 + lane] = w0;
    g_adjp[(size_t)row*64 + 32 + lane] = w1;
}
__global__ __launch_bounds__(256) void split_x_kernel(const float* __restrict__ x) {
    size_t i = (size_t)blockIdx.x * 256 + threadIdx.x;
    float2 v = ((const float2*)x)[i];
    uint32_t hi, lo; split_pair(v.x, v.y, hi, lo);
    ((uint32_t*)g_xh)[i] = hi;
    ((uint32_t*)g_xl)[i] = lo;
}
__global__ __launch_bounds__(128) void transWh_kernel(const float* __restrict__ Wh) {
    const int n = blockIdx.x, t = threadIdx.x;
    const int h = n >> 6, o = n & 63;
    float a = Wh[(size_t)h*NF*DD + (size_t)(2*t)*DD + o];
    float b = Wh[(size_t)h*NF*DD + (size_t)(2*t+1)*DD + o];
    uint32_t hi, lo; split_pair(a, b, hi, lo);
    ((uint32_t*)g_WhT_h)[n*(NF/2) + t] = hi;
    ((uint32_t*)g_WhT_l)[n*(NF/2) + t] = lo;
}
__global__ __launch_bounds__(256) void transWo_kernel(const float* __restrict__ Wo) {
    const int n = blockIdx.x, t = threadIdx.x;
    float a = Wo[(size_t)(2*t)*NO + n];
    float b = Wo[(size_t)(2*t+1)*NO + n];
    uint32_t hi, lo; split_pair(a, b, hi, lo);
    ((uint32_t*)g_WoT_h)[n*(C1/2) + t] = hi;
    ((uint32_t*)g_WoT_l)[n*(C1/2) + t] = lo;
}

// ---------------- GEMM via mma.sync (3-pass bf16 split) ----------------
__device__ __forceinline__ void gemm_mma_body(
    const __nv_bfloat16* __restrict__ Ah, const __nv_bfloat16* __restrict__ Al,
    const __nv_bfloat16* __restrict__ BTh, const __nv_bfloat16* __restrict__ BTl,
    float* __restrict__ Out, int K, int Ncols, int nkt, char* dsm) {
    __nv_bfloat16* sAh = (__nv_bfloat16*)dsm;
    __nv_bfloat16* sAl = sAh + 64*72;
    __nv_bfloat16* sBh = sAl + 64*72;
    __nv_bfloat16* sBl = sBh + 128*72;
    const int tid = threadIdx.x, warp = tid >> 5, lane = tid & 31;
    const int mi = warp >> 1, ni = warp & 1;
    const int m0 = blockIdx.y * 64, n0 = blockIdx.x * 128;
    const uint32_t sAhA = smem_to_u32(sAh), sAlA = smem_to_u32(sAl);
    const uint32_t sBhA = smem_to_u32(sBh), sBlA = smem_to_u32(sBl);
    const int rq = lane >> 2, cq = lane & 3;

    float acc[4][2][4] = {};
    for (int kt = 0; kt < nkt; ++kt) {
        const int k0 = kt * 64;
        __syncthreads();
        #pragma unroll
        for (int rr = 0; rr < 2; ++rr) {
            int idx = tid + rr*256;
            int row = idx >> 3, ch = idx & 7;
            size_t so = (size_t)(m0 + row)*K + k0 + ch*8;
            *(uint4*)(sAh + row*72 + ch*8) = *(const uint4*)(Ah + so);
            *(uint4*)(sAl + row*72 + ch*8) = *(const uint4*)(Al + so);
        }
        #pragma unroll
        for (int rr = 0; rr < 4; ++rr) {
            int idx = tid + rr*256;
            int row = idx >> 3, ch = idx & 7;
            size_t so = (size_t)(n0 + row)*K + k0 + ch*8;
            *(uint4*)(sBh + row*72 + ch*8) = *(const uint4*)(BTh + so);
            *(uint4*)(sBl + row*72 + ch*8) = *(const uint4*)(BTl + so);
        }
        __syncthreads();
        #pragma unroll
        for (int ks = 0; ks < 4; ++ks) {
            const int jb = ks * 16;
            uint32_t ah4[4], al4[4];
            uint32_t aoff = (uint32_t)(((mi*16 + (lane & 15))*72 + jb + (lane >> 4)*8) * 2);
            LDM_X4(ah4, sAhA + aoff);
            LDM_X4(al4, sAlA + aoff);
            #pragma unroll
            for (int np = 0; np < 4; ++np) {
                uint32_t boff = (uint32_t)(((ni*64 + np*16 + (lane & 15))*72 + jb + (lane >> 4)*8) * 2);
                uint32_t bh4[4], bl4[4];
                LDM_X4(bh4, sBhA + boff);
                LDM_X4(bl4, sBlA + boff);
                MMA_BF16(acc[np][0], ah4, bh4[0], bh4[2]);
                MMA_BF16(acc[np][1], ah4, bh4[1], bh4[3]);
                MMA_BF16(acc[np][0], ah4, bl4[0], bl4[2]);
                MMA_BF16(acc[np][1], ah4, bl4[1], bl4[3]);
                MMA_BF16(acc[np][0], al4, bh4[0], bh4[2]);
                MMA_BF16(acc[np][1], al4, bh4[1], bh4[3]);
            }
        }
    }
    const int r0 = m0 + mi*16 + rq, r1 = r0 + 8;
    #pragma unroll
    for (int np = 0; np < 4; ++np)
        #pragma unroll
        for (int n8 = 0; n8 < 2; ++n8) {
            const int c = n0 + ni*64 + np*16 + n8*8 + cq*2;
            const float* a = acc[np][n8];
            *(float2*)&Out[(size_t)r0*Ncols + c] = make_float2(a[0], a[1]);
            *(float2*)&Out[(size_t)r1*Ncols + c] = make_float2(a[2], a[3]);
        }
}
__global__ __launch_bounds__(256) void gemm1_mma_kernel() {
    extern __shared__ __align__(16) char dsm[];
    gemm_mma_body(g_xh, g_xl, g_WhT_h, g_WhT_l, g_h1, NF, C1, NF/64, dsm);
}
__global__ __launch_bounds__(256) void gemm2_mma_kernel() {
    extern __shared__ __align__(16) char dsm[];
    gemm_mma_body(g_z1h, g_z1l, g_WoT_h, g_WoT_l, g_h2, C1, NO, C1/64, dsm);
}

// ---------------- scores ----------------
__global__ __launch_bounds__(256) void scores1_kernel(const float* __restrict__ ah) {
    const int n = blockIdx.x, b = blockIdx.y;
    const int w = threadIdx.x >> 5, lane = threadIdx.x & 31;
    const size_t row = (size_t)b * NN + n;
    const float* hrow = &g_h1[row * C1 + w * DD];
    float v0 = hrow[lane], v1 = hrow[lane + 32];
    const float* a = &ah[w * 2 * DD];
    float s1 = v0 * a[lane] + v1 * a[lane + 32];
    float s2 = v0 * a[DD + lane] + v1 * a[DD + lane + 32];
    #pragma unroll
    for (int s = 16; s; s >>= 1) {
        s1 += __shfl_down_sync(0xFFFFFFFFu, s1, s);
        s2 += __shfl_down_sync(0xFFFFFFFFu, s2, s);
    }
    if (lane == 0) {
        g_ef1[row * NH + w] = make_float2(expf(s1), expf(0.1f * s1));
        g_ef2[row * NH + w] = make_float2(expf(s2), expf(0.1f * s2));
    }
}
__global__ __launch_bounds__(128) void scores2_kernel(const float* __restrict__ ao) {
    __shared__ float s1s[128], s2s[128];
    const int n = blockIdx.x, b = blockIdx.y;
    const size_t row = (size_t)b * NN + n;
    const int t = threadIdx.x;
    float v = g_h2[row * NO + t];
    s1s[t] = v * ao[t];
    s2s[t] = v * ao[NO + t];
    __syncthreads();
    for (int s = 64; s; s >>= 1) {
        if (t < s) { s1s[t] += s1s[t + s]; s2s[t] += s2s[t + s]; }
        __syncthreads();
    }
    if (t == 0) {
        g_ef1o[row] = make_float2(expf(s1s[0]), expf(0.1f * s1s[0]));
        g_ef2o[row] = make_float2(expf(s2s[0]), expf(0.1f * s2s[0]));
    }
}

// ---------------- transpose -> fp16 ----------------
__device__ __forceinline__ void trans_f16(const float* __restrict__ src,
                                          __half* __restrict__ dst, int C) {
    __shared__ float tsm[32][33];
    const int lane = threadIdx.x & 31, ty = threadIdx.x >> 5;
    const int n0 = blockIdx.x * 32, c0 = blockIdx.y * 32, b = blockIdx.z;
    #pragma unroll
    for (int r = 0; r < 4; ++r)
        tsm[ty + r*8][lane] = src[((size_t)b*NN + n0 + ty + r*8)*C + c0 + lane];
    __syncthreads();
    #pragma unroll
    for (int r = 0; r < 4; ++r) {
        float v = tsm[lane][ty + r*8];
        dst[((size_t)b*C + c0 + ty + r*8)*NN + n0 + lane] = __float2half(v);
    }
}
__global__ __launch_bounds__(256) void trans1_kernel() { trans_f16(g_h1, g_h1T, C1); }
__global__ __launch_bounds__(256) void trans2_kernel() { trans_f16(g_h2, g_h2T, NO); }

// ---------------- agg1: fp16 mma.sync, register-prefetch double buffer ----------------
__global__ __launch_bounds__(256) void agg1_mma_kernel(const float* __restrict__ bh) {
    extern __shared__ __align__(16) char dsm[];
    __half* sB = (__half*)dsm;                 // 64*72
    float2* sef = (float2*)(sB + 64*72);       // 64

    const int tid = threadIdx.x, warp = tid >> 5, lane = tid & 31;
    const int head = blockIdx.x, i0 = blockIdx.y * 128, b = blockIdx.z;
    const int iw = i0 + warp * 16;
    const uint32_t sBA = smem_to_u32(sB);
    const int rq = lane >> 2, cq = lane & 3;
    const int srow0 = tid >> 3, sch0 = tid & 7;           // staging coords rr=0
    const int srow1 = (tid + 256) >> 3, sch1 = tid & 7;   // rr=1

    float2 u[2];
    u[0] = g_ef1[((size_t)b*NN + iw + rq)*NH + head];
    u[1] = g_ef1[((size_t)b*NN + iw + rq + 8)*NH + head];
    float lac[2] = {};
    float acc[4][2][4] = {};

    uint4 pB0, pB1; float2 pE;
    {
        pB0 = *(const uint4*)(g_h1T + ((size_t)(b*C1 + head*DD + srow0))*NN + sch0*8);
        pB1 = *(const uint4*)(g_h1T + ((size_t)(b*C1 + head*DD + srow1))*NN + sch1*8);
        if (tid < 64) pE = g_ef2[((size_t)b*NN + tid)*NH + head];
    }
    uint2 mc[2];
    mc[0] = *(const uint2*)&g_adjp[((size_t)b*NN + iw + rq)*64];
    mc[1] = *(const uint2*)&g_adjp[((size_t)b*NN + iw + rq + 8)*64];

    for (int jt = 0; jt < 32; ++jt) {
        // write staged regs into smem
        *(uint4*)(sB + srow0*72 + sch0*8) = pB0;
        *(uint4*)(sB + srow1*72 + sch1*8) = pB1;
        if (tid < 64) sef[tid] = pE;
        __syncthreads();

        // prefetch next tile into regs (overlaps with compute below)
        uint2 mn[2];
        if (jt + 1 < 32) {
            const int jn = (jt + 1) * 64;
            pB0 = *(const uint4*)(g_h1T + ((size_t)(b*C1 + head*DD + srow0))*NN + jn + sch0*8);
            pB1 = *(const uint4*)(g_h1T + ((size_t)(b*C1 + head*DD + srow1))*NN + jn + sch1*8);
            if (tid < 64) pE = g_ef2[((size_t)b*NN + jn + tid)*NH + head];
            mn[0] = *(const uint2*)&g_adjp[((size_t)b*NN + iw + rq)*64 + (jn >> 5)];
            mn[1] = *(const uint2*)&g_adjp[((size_t)b*NN + iw + rq + 8)*64 + (jn >> 5)];
        }

        #pragma unroll
        for (int ks = 0; ks < 4; ++ks) {
            const int jb = ks * 16;
            float4 va = *(const float4*)&sef[jb + 2*cq];
            float4 vb = *(const float4*)&sef[jb + 2*cq + 8];
            uint32_t ahi[4];
            #pragma unroll
            for (int h = 0; h < 2; ++h) {
                uint32_t mw = (ks < 2) ? mc[h].x : mc[h].y;
                const int sh = (ks & 1)*16 + 2*cq;
                const float2 uu = u[h];
                float w0 = ((mw >> sh) & 1u)     ? fmaxf(uu.x*va.x, uu.y*va.y) : 0.0f;
                float w1 = ((mw >> (sh+1)) & 1u) ? fmaxf(uu.x*va.z, uu.y*va.w) : 0.0f;
                float w2 = ((mw >> (sh+8)) & 1u) ? fmaxf(uu.x*vb.x, uu.y*vb.y) : 0.0f;
                float w3 = ((mw >> (sh+9)) & 1u) ? fmaxf(uu.x*vb.z, uu.y*vb.w) : 0.0f;
                uint32_t hA = pack_f16(w0, w1);
                uint32_t hB = pack_f16(w2, w3);
                lac[h] += pair_sum_h(hA) + pair_sum_h(hB);
                ahi[h] = hA;  ahi[h+2] = hB;
            }
            #pragma unroll
            for (int np = 0; np < 4; ++np) {
                uint32_t boff = (uint32_t)(((np*16 + (lane & 15))*72 + jb + (lane >> 4)*8) * 2);
                uint32_t b4[4];
                LDM_X4(b4, sBA + boff);
                MMA_F16(acc[np][0], ahi, b4[0], b4[2]);
                MMA_F16(acc[np][1], ahi, b4[1], b4[3]);
            }
        }
        __syncthreads();   // protect smem before next-iter store
        mc[0] = mn[0]; mc[1] = mn[1];
    }
    #pragma unroll
    for (int h = 0; h < 2; ++h) {
        lac[h] += __shfl_xor_sync(0xFFFFFFFFu, lac[h], 1);
        lac[h] += __shfl_xor_sync(0xFFFFFFFFu, lac[h], 2);
    }
    const float inv0 = 1.0f / lac[0], inv1 = 1.0f / lac[1];
    const int r0 = iw + rq, r1 = r0 + 8;
    #pragma unroll
    for (int np = 0; np < 4; ++np)
        #pragma unroll
        for (int n8 = 0; n8 < 2; ++n8) {
            const int c = np*16 + n8*8 + cq*2;
            const float bb0 = bh[head*DD + c], bb1 = bh[head*DD + c + 1];
            const float* a = acc[np][n8];
            float z00 = a[0]*inv0 + bb0, z01 = a[1]*inv0 + bb1;
            float z10 = a[2]*inv1 + bb0, z11 = a[3]*inv1 + bb1;
            z00 = (z00 > 0.0f) ? z00 : expm1f(z00);
            z01 = (z01 > 0.0f) ? z01 : expm1f(z01);
            z10 = (z10 > 0.0f) ? z10 : expm1f(z10);
            z11 = (z11 > 0.0f) ? z11 : expm1f(z11);
            uint32_t zh, zl;
            split_pair(z00, z01, zh, zl);
            *(uint32_t*)&g_z1h[((size_t)b*NN + r0)*C1 + head*DD + c] = zh;
            *(uint32_t*)&g_z1l[((size_t)b*NN + r0)*C1 + head*DD + c] = zl;
            split_pair(z10, z11, zh, zl);
            *(uint32_t*)&g_z1h[((size_t)b*NN + r1)*C1 + head*DD + c] = zh;
            *(uint32_t*)&g_z1l[((size_t)b*NN + r1)*C1 + head*DD + c] = zl;
        }
}

// ---------------- agg2: fp16 mma.sync, N=128, register-prefetch ----------------
__global__ __launch_bounds__(128) void agg2_mma_kernel(const float* __restrict__ bo,
                                                       float* __restrict__ out) {
    extern __shared__ __align__(16) char dsm[];
    __half* sB = (__half*)dsm;                 // 128*72
    float2* sef = (float2*)(sB + 128*72);      // 64

    const int tid = threadIdx.x, warp = tid >> 5, lane = tid & 31;
    const int i0 = blockIdx.x * 32, b = blockIdx.y;
    const int mi = warp >> 1, ni = warp & 1;
    const int iw = i0 + mi * 16;
    const uint32_t sBA = smem_to_u32(sB);
    const int rq = lane >> 2, cq = lane & 3;

    float2 u[2];
    u[0] = g_ef1o[(size_t)b*NN + iw + rq];
    u[1] = g_ef1o[(size_t)b*NN + iw + rq + 8];
    float lac[2] = {};
    float acc[4][2][4] = {};

    uint4 pB[8]; float2 pE;
    #pragma unroll
    for (int rr = 0; rr < 8; ++rr) {
        int idx = tid + rr*128;
        int row = idx >> 3, ch = idx & 7;
        pB[rr] = *(const uint4*)(g_h2T + ((size_t)(b*NO + row))*NN + ch*8);
    }
    if (tid < 64) pE = g_ef2o[(size_t)b*NN + tid];
    uint2 mc[2];
    mc[0] = *(const uint2*)&g_adjp[((size_t)b*NN + iw + rq)*64];
    mc[1] = *(const uint2*)&g_adjp[((size_t)b*NN + iw + rq + 8)*64];

    for (int jt = 0; jt < 32; ++jt) {
        #pragma unroll
        for (int rr = 0; rr < 8; ++rr) {
            int idx = tid + rr*128;
            int row = idx >> 3, ch = idx & 7;
            *(uint4*)(sB + row*72 + ch*8) = pB[rr];
        }
        if (tid < 64) sef[tid] = pE;
        __syncthreads();

        uint2 mn[2];
        if (jt + 1 < 32) {
            const int jn = (jt + 1) * 64;
            #pragma unroll
            for (int rr = 0; rr < 8; ++rr) {
                int idx = tid + rr*128;
                int row = idx >> 3, ch = idx & 7;
                pB[rr] = *(const uint4*)(g_h2T + ((size_t)(b*NO + row))*NN + jn + ch*8);
            }
            if (tid < 64) pE = g_ef2o[(size_t)b*NN + jn + tid];
            mn[0] = *(const uint2*)&g_adjp[((size_t)b*NN + iw + rq)*64 + (jn >> 5)];
            mn[1] = *(const uint2*)&g_adjp[((size_t)b*NN + iw + rq + 8)*64 + (jn >> 5)];
        }

        #pragma unroll
        for (int ks = 0; ks < 4; ++ks) {
            const int jb = ks * 16;
            float4 va = *(const float4*)&sef[jb + 2*cq];
            float4 vb = *(const float4*)&sef[jb + 2*cq + 8];
            uint32_t ahi[4];
            #pragma unroll
            for (int h = 0; h < 2; ++h) {
                uint32_t mw = (ks < 2) ? mc[h].x : mc[h].y;
                const int sh = (ks & 1)*16 + 2*cq;
                const float2 uu = u[h];
                float w0 = ((mw >> sh) & 1u)     ? fmaxf(uu.x*va.x, uu.y*va.y) : 0.0f;
                float w1 = ((mw >> (sh+1)) & 1u) ? fmaxf(uu.x*va.z, uu.y*va.w) : 0.0f;
                float w2 = ((mw >> (sh+8)) & 1u) ? fmaxf(uu.x*vb.x, uu.y*vb.y) : 0.0f;
                float w3 = ((mw >> (sh+9)) & 1u) ? fmaxf(uu.x*vb.z, uu.y*vb.w) : 0.0f;
                uint32_t hA = pack_f16(w0, w1);
                uint32_t hB = pack_f16(w2, w3);
                lac[h] += pair_sum_h(hA) + pair_sum_h(hB);
                ahi[h] = hA;  ahi[h+2] = hB;
            }
            #pragma unroll
            for (int np = 0; np < 4; ++np) {
                uint32_t boff = (uint32_t)(((ni*64 + np*16 + (lane & 15))*72 + jb + (lane >> 4)*8) * 2);
                uint32_t b4[4];
                LDM_X4(b4, sBA + boff);
                MMA_F16(acc[np][0], ahi, b4[0], b4[2]);
                MMA_F16(acc[np][1], ahi, b4[1], b4[3]);
            }
        }
        __syncthreads();
        mc[0] = mn[0]; mc[1] = mn[1];
    }
    #pragma unroll
    for (int h = 0; h < 2; ++h) {
        lac[h] += __shfl_xor_sync(0xFFFFFFFFu, lac[h], 1);
        lac[h] += __shfl_xor_sync(0xFFFFFFFFu, lac[h], 2);
    }
    const float inv0 = 1.0f / lac[0], inv1 = 1.0f / lac[1];
    const int r0 = iw + rq, r1 = r0 + 8;
    #pragma unroll
    for (int np = 0; np < 4; ++np)
        #pragma unroll
        for (int n8 = 0; n8 < 2; ++n8) {
            const int c = ni*64 + np*16 + n8*8 + cq*2;
            const float bb0 = bo[c], bb1 = bo[c + 1];
            const float* a = acc[np][n8];
            float z00 = fmaxf(a[0]*inv0 + bb0, 0.0f);
            float z01 = fmaxf(a[1]*inv0 + bb1, 0.0f);
            float z10 = fmaxf(a[2]*inv1 + bb0, 0.0f);
            float z11 = fmaxf(a[3]*inv1 + bb1, 0.0f);
            *(float2*)&out[((size_t)b*NN + r0)*NO + c] = make_float2(z00, z01);
            *(float2*)&out[((size_t)b*NN + r1)*NO + c] = make_float2(z10, z11);
        }
}

// ---------------------------------------------------------------------------
extern "C" void kernel_launch(void* const* d_in, const int* in_sizes, int n_in,
                              void* d_out, int out_size) {
    const float* x   = (const float*)d_in[0];
    const int*   adj = (const int*)  d_in[1];
    const float* Wh  = (const float*)d_in[2];
    const float* ah  = (const float*)d_in[3];
    const float* bh  = (const float*)d_in[4];
    const float* Wo  = (const float*)d_in[5];
    const float* ao  = (const float*)d_in[6];
    const float* bo  = (const float*)d_in[7];
    float* out = (float*)d_out;

    const int smem_gemm = (64 + 64 + 128 + 128) * 72 * 2;   // 55296
    const int smem1 = 64*72*2 + 64*8;      // 9728
    const int smem2 = 128*72*2 + 64*8;     // 18944
    cudaFuncSetAttribute(gemm1_mma_kernel, cudaFuncAttributeMaxDynamicSharedMemorySize, smem_gemm);
    cudaFuncSetAttribute(gemm2_mma_kernel, cudaFuncAttributeMaxDynamicSharedMemorySize, smem_gemm);
    cudaFuncSetAttribute(agg1_mma_kernel, cudaFuncAttributeMaxDynamicSharedMemorySize, smem1);
    cudaFuncSetAttribute(agg2_mma_kernel, cudaFuncAttributeMaxDynamicSharedMemorySize, smem2);

    pack_adj_kernel<<<(BB*NN)/8, 256>>>(adj);
    split_x_kernel<<<(BB*NN*NF/2)/256, 256>>>(x);
    transWh_kernel<<<C1, 128>>>(Wh);
    transWo_kernel<<<NO, 256>>>(Wo);

    gemm1_mma_kernel<<<dim3(C1/128, (BB*NN)/64), 256, smem_gemm>>>();
    scores1_kernel<<<dim3(NN, BB), 256>>>(ah);
    trans1_kernel<<<dim3(NN / 32, C1 / 32, BB), 256>>>();
    agg1_mma_kernel<<<dim3(NH, NN / 128, BB), 256, smem1>>>(bh);

    gemm2_mma_kernel<<<dim3(NO/128, (BB*NN)/64), 256, smem_gemm>>>();
    scores2_kernel<<<dim3(NN, BB), 128>>>(ao);
    trans2_kernel<<<dim3(NN / 32, NO / 32, BB), 256>>>();
    agg2_mma_kernel<<<dim3(NN / 32, BB), 128, smem2>>>(bo, out);
}

// round 17
// speedup vs baseline: 1.6859x; 1.1112x over previous
#include <cuda_runtime.h>
#include <cuda_bf16.h>
#include <cuda_fp16.h>
#include <math.h>
#include <stdint.h>

#define BB 4
#define NN 2048
#define NF 256
#define NH 8
#define DD 64
#define C1 512
#define NO 128

__device__ float2 g_ef1[BB*NN*NH];
__device__ float2 g_ef2[BB*NN*NH];
__device__ float2 g_ef1o[BB*NN];
__device__ float2 g_ef2o[BB*NN];
__device__ __half g_h1T[BB*C1*NN];
__device__ __half g_h2T[BB*NO*NN];
__device__ uint32_t g_adjp[BB*NN*(NN/32)];
__device__ __nv_bfloat16 g_xh[BB*NN*NF],  g_xl[BB*NN*NF];
__device__ __nv_bfloat16 g_WhT_h[C1*NF],  g_WhT_l[C1*NF];
__device__ __nv_bfloat16 g_WoT_h[NO*C1],  g_WoT_l[NO*C1];
__device__ __nv_bfloat16 g_z1h[BB*NN*C1], g_z1l[BB*NN*C1];

// ---------------- helpers ----------------
__device__ __forceinline__ uint32_t smem_to_u32(const void* p) {
    uint32_t a;
    asm("{ .reg .u64 t; cvta.to.shared.u64 t, %1; cvt.u32.u64 %0, t; }" : "=r"(a) : "l"(p));
    return a;
}
#define LDM_X4(r, addr) \
    asm volatile("ldmatrix.sync.aligned.m8n8.x4.shared.b16 {%0,%1,%2,%3}, [%4];" \
        : "=r"((r)[0]), "=r"((r)[1]), "=r"((r)[2]), "=r"((r)[3]) : "r"(addr))
#define MMA_BF16(d, a, b0, b1) \
    asm volatile("mma.sync.aligned.m16n8k16.row.col.f32.bf16.bf16.f32 " \
        "{%0,%1,%2,%3}, {%4,%5,%6,%7}, {%8,%9}, {%0,%1,%2,%3};" \
        : "+f"((d)[0]), "+f"((d)[1]), "+f"((d)[2]), "+f"((d)[3]) \
        : "r"((a)[0]), "r"((a)[1]), "r"((a)[2]), "r"((a)[3]), "r"(b0), "r"(b1))
#define MMA_F16(d, a, b0, b1) \
    asm volatile("mma.sync.aligned.m16n8k16.row.col.f32.f16.f16.f32 " \
        "{%0,%1,%2,%3}, {%4,%5,%6,%7}, {%8,%9}, {%0,%1,%2,%3};" \
        : "+f"((d)[0]), "+f"((d)[1]), "+f"((d)[2]), "+f"((d)[3]) \
        : "r"((a)[0]), "r"((a)[1]), "r"((a)[2]), "r"((a)[3]), "r"(b0), "r"(b1))

__device__ __forceinline__ uint32_t pack_bf16(float e0, float e1) {
    uint32_t r;
    asm("cvt.rn.satfinite.bf16x2.f32 %0, %1, %2;" : "=r"(r) : "f"(e1), "f"(e0));
    return r;
}
__device__ __forceinline__ uint32_t pack_f16(float e0, float e1) {
    uint32_t r;
    asm("cvt.rn.f16x2.f32 %0, %1, %2;" : "=r"(r) : "f"(e1), "f"(e0));
    return r;
}
__device__ __forceinline__ void split_pair(float w0, float w1, uint32_t& hi, uint32_t& lo) {
    hi = pack_bf16(w0, w1);
    float r0 = w0 - __uint_as_float(hi << 16);
    float r1 = w1 - __uint_as_float(hi & 0xFFFF0000u);
    lo = pack_bf16(r0, r1);
}
__device__ __forceinline__ float pair_sum_h(uint32_t p) {
    __half2 h = *reinterpret_cast<__half2*>(&p);
    float2 f = __half22float2(h);
    return f.x + f.y;
}

// ---------------- prep ----------------
__global__ __launch_bounds__(256) void pack_adj_kernel(const int* __restrict__ adj) {
    const int lane = threadIdx.x & 31, warp = threadIdx.x >> 5;
    const int row = blockIdx.x * 8 + warp;
    const size_t base = (size_t)row * NN;
    uint32_t w0 = 0, w1 = 0;
    #pragma unroll 8
    for (int g = 0; g < 64; ++g) {
        uint32_t bits = __ballot_sync(0xFFFFFFFFu, adj[base + g*32 + lane] > 0);
        if (g < 32) { if (lane == g) w0 = bits; }
        else        { if (lane == g - 32) w1 = bits; }
    }
    g_adjp[(size_t)row*64 + lane] = w0;
    g_adjp[(size_t)row*64 + 32 + lane] = w1;
}
__global__ __launch_bounds__(256) void split_x_kernel(const float* __restrict__ x) {
    size_t i = (size_t)blockIdx.x * 256 + threadIdx.x;
    float2 v = ((const float2*)x)[i];
    uint32_t hi, lo; split_pair(v.x, v.y, hi, lo);
    ((uint32_t*)g_xh)[i] = hi;
    ((uint32_t*)g_xl)[i] = lo;
}
__global__ __launch_bounds__(128) void transWh_kernel(const float* __restrict__ Wh) {
    const int n = blockIdx.x, t = threadIdx.x;
    const int h = n >> 6, o = n & 63;
    float a = Wh[(size_t)h*NF*DD + (size_t)(2*t)*DD + o];
    float b = Wh[(size_t)h*NF*DD + (size_t)(2*t+1)*DD + o];
    uint32_t hi, lo; split_pair(a, b, hi, lo);
    ((uint32_t*)g_WhT_h)[n*(NF/2) + t] = hi;
    ((uint32_t*)g_WhT_l)[n*(NF/2) + t] = lo;
}
__global__ __launch_bounds__(256) void transWo_kernel(const float* __restrict__ Wo) {
    const int n = blockIdx.x, t = threadIdx.x;
    float a = Wo[(size_t)(2*t)*NO + n];
    float b = Wo[(size_t)(2*t+1)*NO + n];
    uint32_t hi, lo; split_pair(a, b, hi, lo);
    ((uint32_t*)g_WoT_h)[n*(C1/2) + t] = hi;
    ((uint32_t*)g_WoT_l)[n*(C1/2) + t] = lo;
}

// ---------------- GEMM mainloop (3-pass bf16 split) -> acc ----------------
#define GEMM_MAINLOOP(Ah, Al, BTh, BTl, K, NKT)                                     \
    __nv_bfloat16* sAh = (__nv_bfloat16*)dsm;                                       \
    __nv_bfloat16* sAl = sAh + 64*72;                                               \
    __nv_bfloat16* sBh = sAl + 64*72;                                               \
    __nv_bfloat16* sBl = sBh + 128*72;                                              \
    const uint32_t sAhA = smem_to_u32(sAh), sAlA = smem_to_u32(sAl);                \
    const uint32_t sBhA = smem_to_u32(sBh), sBlA = smem_to_u32(sBl);                \
    float acc[4][2][4] = {};                                                        \
    for (int kt = 0; kt < (NKT); ++kt) {                                            \
        const int k0 = kt * 64;                                                     \
        __syncthreads();                                                            \
        _Pragma("unroll")                                                           \
        for (int rr = 0; rr < 2; ++rr) {                                            \
            int idx = tid + rr*256;                                                 \
            int row = idx >> 3, ch = idx & 7;                                       \
            size_t so = (size_t)(m0 + row)*(K) + k0 + ch*8;                         \
            *(uint4*)(sAh + row*72 + ch*8) = *(const uint4*)((Ah) + so);            \
            *(uint4*)(sAl + row*72 + ch*8) = *(const uint4*)((Al) + so);            \
        }                                                                           \
        _Pragma("unroll")                                                           \
        for (int rr = 0; rr < 4; ++rr) {                                            \
            int idx = tid + rr*256;                                                 \
            int row = idx >> 3, ch = idx & 7;                                       \
            size_t so = (size_t)(n0 + row)*(K) + k0 + ch*8;                         \
            *(uint4*)(sBh + row*72 + ch*8) = *(const uint4*)((BTh) + so);           \
            *(uint4*)(sBl + row*72 + ch*8) = *(const uint4*)((BTl) + so);           \
        }                                                                           \
        __syncthreads();                                                            \
        _Pragma("unroll")                                                           \
        for (int ks = 0; ks < 4; ++ks) {                                            \
            const int jb = ks * 16;                                                 \
            uint32_t ah4[4], al4[4];                                                \
            uint32_t aoff = (uint32_t)(((mi*16 + (lane & 15))*72 + jb + (lane >> 4)*8) * 2); \
            LDM_X4(ah4, sAhA + aoff);                                               \
            LDM_X4(al4, sAlA + aoff);                                               \
            _Pragma("unroll")                                                       \
            for (int np = 0; np < 4; ++np) {                                        \
                uint32_t boff = (uint32_t)(((ni*64 + np*16 + (lane & 15))*72 + jb + (lane >> 4)*8) * 2); \
                uint32_t bh4[4], bl4[4];                                            \
                LDM_X4(bh4, sBhA + boff);                                           \
                LDM_X4(bl4, sBlA + boff);                                           \
                MMA_BF16(acc[np][0], ah4, bh4[0], bh4[2]);                          \
                MMA_BF16(acc[np][1], ah4, bh4[1], bh4[3]);                          \
                MMA_BF16(acc[np][0], ah4, bl4[0], bl4[2]);                          \
                MMA_BF16(acc[np][1], ah4, bl4[1], bl4[3]);                          \
                MMA_BF16(acc[np][0], al4, bh4[0], bh4[2]);                          \
                MMA_BF16(acc[np][1], al4, bh4[1], bh4[3]);                          \
            }                                                                       \
        }                                                                           \
    }

// ---------------- gemm1 fused: h1 = x@Wh, + scores1 + h1T fp16 transpose ----------------
__global__ __launch_bounds__(256) void gemm1_fused_kernel(const float* __restrict__ ah) {
    extern __shared__ __align__(16) char dsm[];
    const int tid = threadIdx.x, warp = tid >> 5, lane = tid & 31;
    const int mi = warp >> 1, ni = warp & 1;
    const int m0 = blockIdx.y * 64, n0 = blockIdx.x * 128;
    const int rq = lane >> 2, cq = lane & 3;

    GEMM_MAINLOOP(g_xh, g_xl, g_WhT_h, g_WhT_l, NF, NF/64)

    // ---- scores: warp's ni-half = one full head (64 cols) ----
    const int head = (n0 >> 6) + ni;
    const float* a1 = ah + head*2*DD;
    const float* a2 = a1 + DD;
    float s1r0 = 0, s1r1 = 0, s2r0 = 0, s2r1 = 0;
    #pragma unroll
    for (int np = 0; np < 4; ++np)
        #pragma unroll
        for (int n8 = 0; n8 < 2; ++n8) {
            const int cl = np*16 + n8*8 + cq*2;
            float a10 = a1[cl], a11 = a1[cl+1];
            float a20 = a2[cl], a21 = a2[cl+1];
            const float* a = acc[np][n8];
            s1r0 += a[0]*a10 + a[1]*a11;  s1r1 += a[2]*a10 + a[3]*a11;
            s2r0 += a[0]*a20 + a[1]*a21;  s2r1 += a[2]*a20 + a[3]*a21;
        }
    #pragma unroll
    for (int s = 1; s <= 2; s <<= 1) {
        s1r0 += __shfl_xor_sync(0xFFFFFFFFu, s1r0, s);
        s1r1 += __shfl_xor_sync(0xFFFFFFFFu, s1r1, s);
        s2r0 += __shfl_xor_sync(0xFFFFFFFFu, s2r0, s);
        s2r1 += __shfl_xor_sync(0xFFFFFFFFu, s2r1, s);
    }
    if (cq == 0) {
        const size_t row0 = (size_t)m0 + mi*16 + rq, row1 = row0 + 8;
        g_ef1[row0*NH + head] = make_float2(expf(s1r0), expf(0.1f*s1r0));
        g_ef2[row0*NH + head] = make_float2(expf(s2r0), expf(0.1f*s2r0));
        g_ef1[row1*NH + head] = make_float2(expf(s1r1), expf(0.1f*s1r1));
        g_ef2[row1*NH + head] = make_float2(expf(s2r1), expf(0.1f*s2r1));
    }

    // ---- fp16 transpose via smem, write g_h1T ----
    __syncthreads();                    // mainloop smem reads done
    __half* sT = (__half*)dsm;          // [128][72]
    #pragma unroll
    for (int np = 0; np < 4; ++np)
        #pragma unroll
        for (int n8 = 0; n8 < 2; ++n8) {
            const int cb = ni*64 + np*16 + n8*8 + cq*2;
            const int rl0 = mi*16 + rq, rl1 = rl0 + 8;
            const float* a = acc[np][n8];
            sT[cb*72 + rl0]     = __float2half(a[0]);
            sT[(cb+1)*72 + rl0] = __float2half(a[1]);
            sT[cb*72 + rl1]     = __float2half(a[2]);
            sT[(cb+1)*72 + rl1] = __float2half(a[3]);
        }
    __syncthreads();
    const int bglob = m0 >> 11;          // m0 / NN
    const int nbase = m0 & (NN - 1);
    #pragma unroll
    for (int it = 0; it < 4; ++it) {
        int idx = tid + it*256;
        int crow = idx >> 3, ch = idx & 7;
        uint4 v = *(uint4*)(sT + crow*72 + ch*8);
        *(uint4*)(g_h1T + ((size_t)(bglob*C1 + n0 + crow))*NN + nbase + ch*8) = v;
    }
}

// ---------------- gemm2 fused: h2 = z1@Wo, + scores2 + h2T fp16 transpose ----------------
__global__ __launch_bounds__(256) void gemm2_fused_kernel(const float* __restrict__ ao) {
    extern __shared__ __align__(16) char dsm[];
    const int tid = threadIdx.x, warp = tid >> 5, lane = tid & 31;
    const int mi = warp >> 1, ni = warp & 1;
    const int m0 = blockIdx.y * 64, n0 = 0;
    const int rq = lane >> 2, cq = lane & 3;

    GEMM_MAINLOOP(g_z1h, g_z1l, g_WoT_h, g_WoT_l, C1, C1/64)

    // ---- scores: need both ni halves -> smem partials ----
    float s1r0 = 0, s1r1 = 0, s2r0 = 0, s2r1 = 0;
    #pragma unroll
    for (int np = 0; np < 4; ++np)
        #pragma unroll
        for (int n8 = 0; n8 < 2; ++n8) {
            const int c = ni*64 + np*16 + n8*8 + cq*2;
            float a10 = ao[c], a11 = ao[c+1];
            float a20 = ao[NO+c], a21 = ao[NO+c+1];
            const float* a = acc[np][n8];
            s1r0 += a[0]*a10 + a[1]*a11;  s1r1 += a[2]*a10 + a[3]*a11;
            s2r0 += a[0]*a20 + a[1]*a21;  s2r1 += a[2]*a20 + a[3]*a21;
        }
    #pragma unroll
    for (int s = 1; s <= 2; s <<= 1) {
        s1r0 += __shfl_xor_sync(0xFFFFFFFFu, s1r0, s);
        s1r1 += __shfl_xor_sync(0xFFFFFFFFu, s1r1, s);
        s2r0 += __shfl_xor_sync(0xFFFFFFFFu, s2r0, s);
        s2r1 += __shfl_xor_sync(0xFFFFFFFFu, s2r1, s);
    }
    __syncthreads();                    // mainloop smem reads done
    __half* sT = (__half*)dsm;          // [128][72] = 18432 B
    float* sP = (float*)(dsm + 128*72*2);  // [64 rows][2 ni][2 scores]
    if (cq == 0) {
        const int rl0 = mi*16 + rq, rl1 = rl0 + 8;
        sP[(rl0*2 + ni)*2 + 0] = s1r0;  sP[(rl0*2 + ni)*2 + 1] = s2r0;
        sP[(rl1*2 + ni)*2 + 0] = s1r1;  sP[(rl1*2 + ni)*2 + 1] = s2r1;
    }
    // ---- fp16 transpose staging ----
    #pragma unroll
    for (int np = 0; np < 4; ++np)
        #pragma unroll
        for (int n8 = 0; n8 < 2; ++n8) {
            const int cb = ni*64 + np*16 + n8*8 + cq*2;
            const int rl0 = mi*16 + rq, rl1 = rl0 + 8;
            const float* a = acc[np][n8];
            sT[cb*72 + rl0]     = __float2half(a[0]);
            sT[(cb+1)*72 + rl0] = __float2half(a[1]);
            sT[cb*72 + rl1]     = __float2half(a[2]);
            sT[(cb+1)*72 + rl1] = __float2half(a[3]);
        }
    __syncthreads();
    const int bglob = m0 >> 11;
    const int nbase = m0 & (NN - 1);
    #pragma unroll
    for (int it = 0; it < 4; ++it) {
        int idx = tid + it*256;
        int crow = idx >> 3, ch = idx & 7;
        uint4 v = *(uint4*)(sT + crow*72 + ch*8);
        *(uint4*)(g_h2T + ((size_t)(bglob*NO + crow))*NN + nbase + ch*8) = v;
    }
    if (tid < 64) {
        float s1 = sP[(tid*2 + 0)*2 + 0] + sP[(tid*2 + 1)*2 + 0];
        float s2 = sP[(tid*2 + 0)*2 + 1] + sP[(tid*2 + 1)*2 + 1];
        g_ef1o[(size_t)m0 + tid] = make_float2(expf(s1), expf(0.1f*s1));
        g_ef2o[(size_t)m0 + tid] = make_float2(expf(s2), expf(0.1f*s2));
    }
}

// ---------------- agg1: fp16 mma.sync, register-prefetch (R16, unchanged) ----------------
__global__ __launch_bounds__(256) void agg1_mma_kernel(const float* __restrict__ bh) {
    extern __shared__ __align__(16) char dsm[];
    __half* sB = (__half*)dsm;
    float2* sef = (float2*)(sB + 64*72);

    const int tid = threadIdx.x, warp = tid >> 5, lane = tid & 31;
    const int head = blockIdx.x, i0 = blockIdx.y * 128, b = blockIdx.z;
    const int iw = i0 + warp * 16;
    const uint32_t sBA = smem_to_u32(sB);
    const int rq = lane >> 2, cq = lane & 3;
    const int srow0 = tid >> 3, sch0 = tid & 7;
    const int srow1 = (tid + 256) >> 3, sch1 = tid & 7;

    float2 u[2];
    u[0] = g_ef1[((size_t)b*NN + iw + rq)*NH + head];
    u[1] = g_ef1[((size_t)b*NN + iw + rq + 8)*NH + head];
    float lac[2] = {};
    float acc[4][2][4] = {};

    uint4 pB0, pB1; float2 pE;
    {
        pB0 = *(const uint4*)(g_h1T + ((size_t)(b*C1 + head*DD + srow0))*NN + sch0*8);
        pB1 = *(const uint4*)(g_h1T + ((size_t)(b*C1 + head*DD + srow1))*NN + sch1*8);
        if (tid < 64) pE = g_ef2[((size_t)b*NN + tid)*NH + head];
    }
    uint2 mc[2];
    mc[0] = *(const uint2*)&g_adjp[((size_t)b*NN + iw + rq)*64];
    mc[1] = *(const uint2*)&g_adjp[((size_t)b*NN + iw + rq + 8)*64];

    for (int jt = 0; jt < 32; ++jt) {
        *(uint4*)(sB + srow0*72 + sch0*8) = pB0;
        *(uint4*)(sB + srow1*72 + sch1*8) = pB1;
        if (tid < 64) sef[tid] = pE;
        __syncthreads();

        uint2 mn[2];
        if (jt + 1 < 32) {
            const int jn = (jt + 1) * 64;
            pB0 = *(const uint4*)(g_h1T + ((size_t)(b*C1 + head*DD + srow0))*NN + jn + sch0*8);
            pB1 = *(const uint4*)(g_h1T + ((size_t)(b*C1 + head*DD + srow1))*NN + jn + sch1*8);
            if (tid < 64) pE = g_ef2[((size_t)b*NN + jn + tid)*NH + head];
            mn[0] = *(const uint2*)&g_adjp[((size_t)b*NN + iw + rq)*64 + (jn >> 5)];
            mn[1] = *(const uint2*)&g_adjp[((size_t)b*NN + iw + rq + 8)*64 + (jn >> 5)];
        }

        #pragma unroll
        for (int ks = 0; ks < 4; ++ks) {
            const int jb = ks * 16;
            float4 va = *(const float4*)&sef[jb + 2*cq];
            float4 vb = *(const float4*)&sef[jb + 2*cq + 8];
            uint32_t ahi[4];
            #pragma unroll
            for (int h = 0; h < 2; ++h) {
                uint32_t mw = (ks < 2) ? mc[h].x : mc[h].y;
                const int sh = (ks & 1)*16 + 2*cq;
                const float2 uu = u[h];
                float w0 = ((mw >> sh) & 1u)     ? fmaxf(uu.x*va.x, uu.y*va.y) : 0.0f;
                float w1 = ((mw >> (sh+1)) & 1u) ? fmaxf(uu.x*va.z, uu.y*va.w) : 0.0f;
                float w2 = ((mw >> (sh+8)) & 1u) ? fmaxf(uu.x*vb.x, uu.y*vb.y) : 0.0f;
                float w3 = ((mw >> (sh+9)) & 1u) ? fmaxf(uu.x*vb.z, uu.y*vb.w) : 0.0f;
                uint32_t hA = pack_f16(w0, w1);
                uint32_t hB = pack_f16(w2, w3);
                lac[h] += pair_sum_h(hA) + pair_sum_h(hB);
                ahi[h] = hA;  ahi[h+2] = hB;
            }
            #pragma unroll
            for (int np = 0; np < 4; ++np) {
                uint32_t boff = (uint32_t)(((np*16 + (lane & 15))*72 + jb + (lane >> 4)*8) * 2);
                uint32_t b4[4];
                LDM_X4(b4, sBA + boff);
                MMA_F16(acc[np][0], ahi, b4[0], b4[2]);
                MMA_F16(acc[np][1], ahi, b4[1], b4[3]);
            }
        }
        __syncthreads();
        mc[0] = mn[0]; mc[1] = mn[1];
    }
    #pragma unroll
    for (int h = 0; h < 2; ++h) {
        lac[h] += __shfl_xor_sync(0xFFFFFFFFu, lac[h], 1);
        lac[h] += __shfl_xor_sync(0xFFFFFFFFu, lac[h], 2);
    }
    const float inv0 = 1.0f / lac[0], inv1 = 1.0f / lac[1];
    const int r0 = iw + rq, r1 = r0 + 8;
    #pragma unroll
    for (int np = 0; np < 4; ++np)
        #pragma unroll
        for (int n8 = 0; n8 < 2; ++n8) {
            const int c = np*16 + n8*8 + cq*2;
            const float bb0 = bh[head*DD + c], bb1 = bh[head*DD + c + 1];
            const float* a = acc[np][n8];
            float z00 = a[0]*inv0 + bb0, z01 = a[1]*inv0 + bb1;
            float z10 = a[2]*inv1 + bb0, z11 = a[3]*inv1 + bb1;
            z00 = (z00 > 0.0f) ? z00 : expm1f(z00);
            z01 = (z01 > 0.0f) ? z01 : expm1f(z01);
            z10 = (z10 > 0.0f) ? z10 : expm1f(z10);
            z11 = (z11 > 0.0f) ? z11 : expm1f(z11);
            uint32_t zh, zl;
            split_pair(z00, z01, zh, zl);
            *(uint32_t*)&g_z1h[((size_t)b*NN + r0)*C1 + head*DD + c] = zh;
            *(uint32_t*)&g_z1l[((size_t)b*NN + r0)*C1 + head*DD + c] = zl;
            split_pair(z10, z11, zh, zl);
            *(uint32_t*)&g_z1h[((size_t)b*NN + r1)*C1 + head*DD + c] = zh;
            *(uint32_t*)&g_z1l[((size_t)b*NN + r1)*C1 + head*DD + c] = zl;
        }
}

// ---------------- agg2: fp16 mma.sync, N=128, register-prefetch (R16, unchanged) ----------------
__global__ __launch_bounds__(128) void agg2_mma_kernel(const float* __restrict__ bo,
                                                       float* __restrict__ out) {
    extern __shared__ __align__(16) char dsm[];
    __half* sB = (__half*)dsm;
    float2* sef = (float2*)(sB + 128*72);

    const int tid = threadIdx.x, warp = tid >> 5, lane = tid & 31;
    const int i0 = blockIdx.x * 32, b = blockIdx.y;
    const int mi = warp >> 1, ni = warp & 1;
    const int iw = i0 + mi * 16;
    const uint32_t sBA = smem_to_u32(sB);
    const int rq = lane >> 2, cq = lane & 3;

    float2 u[2];
    u[0] = g_ef1o[(size_t)b*NN + iw + rq];
    u[1] = g_ef1o[(size_t)b*NN + iw + rq + 8];
    float lac[2] = {};
    float acc[4][2][4] = {};

    uint4 pB[8]; float2 pE;
    #pragma unroll
    for (int rr = 0; rr < 8; ++rr) {
        int idx = tid + rr*128;
        int row = idx >> 3, ch = idx & 7;
        pB[rr] = *(const uint4*)(g_h2T + ((size_t)(b*NO + row))*NN + ch*8);
    }
    if (tid < 64) pE = g_ef2o[(size_t)b*NN + tid];
    uint2 mc[2];
    mc[0] = *(const uint2*)&g_adjp[((size_t)b*NN + iw + rq)*64];
    mc[1] = *(const uint2*)&g_adjp[((size_t)b*NN + iw + rq + 8)*64];

    for (int jt = 0; jt < 32; ++jt) {
        #pragma unroll
        for (int rr = 0; rr < 8; ++rr) {
            int idx = tid + rr*128;
            int row = idx >> 3, ch = idx & 7;
            *(uint4*)(sB + row*72 + ch*8) = pB[rr];
        }
        if (tid < 64) sef[tid] = pE;
        __syncthreads();

        uint2 mn[2];
        if (jt + 1 < 32) {
            const int jn = (jt + 1) * 64;
            #pragma unroll
            for (int rr = 0; rr < 8; ++rr) {
                int idx = tid + rr*128;
                int row = idx >> 3, ch = idx & 7;
                pB[rr] = *(const uint4*)(g_h2T + ((size_t)(b*NO + row))*NN + jn + ch*8);
            }
            if (tid < 64) pE = g_ef2o[(size_t)b*NN + jn + tid];
            mn[0] = *(const uint2*)&g_adjp[((size_t)b*NN + iw + rq)*64 + (jn >> 5)];
            mn[1] = *(const uint2*)&g_adjp[((size_t)b*NN + iw + rq + 8)*64 + (jn >> 5)];
        }

        #pragma unroll
        for (int ks = 0; ks < 4; ++ks) {
            const int jb = ks * 16;
            float4 va = *(const float4*)&sef[jb + 2*cq];
            float4 vb = *(const float4*)&sef[jb + 2*cq + 8];
            uint32_t ahi[4];
            #pragma unroll
            for (int h = 0; h < 2; ++h) {
                uint32_t mw = (ks < 2) ? mc[h].x : mc[h].y;
                const int sh = (ks & 1)*16 + 2*cq;
                const float2 uu = u[h];
                float w0 = ((mw >> sh) & 1u)     ? fmaxf(uu.x*va.x, uu.y*va.y) : 0.0f;
                float w1 = ((mw >> (sh+1)) & 1u) ? fmaxf(uu.x*va.z, uu.y*va.w) : 0.0f;
                float w2 = ((mw >> (sh+8)) & 1u) ? fmaxf(uu.x*vb.x, uu.y*vb.y) : 0.0f;
                float w3 = ((mw >> (sh+9)) & 1u) ? fmaxf(uu.x*vb.z, uu.y*vb.w) : 0.0f;
                uint32_t hA = pack_f16(w0, w1);
                uint32_t hB = pack_f16(w2, w3);
                lac[h] += pair_sum_h(hA) + pair_sum_h(hB);
                ahi[h] = hA;  ahi[h+2] = hB;
            }
            #pragma unroll
            for (int np = 0; np < 4; ++np) {
                uint32_t boff = (uint32_t)(((ni*64 + np*16 + (lane & 15))*72 + jb + (lane >> 4)*8) * 2);
                uint32_t b4[4];
                LDM_X4(b4, sBA + boff);
                MMA_F16(acc[np][0], ahi, b4[0], b4[2]);
                MMA_F16(acc[np][1], ahi, b4[1], b4[3]);
            }
        }
        __syncthreads();
        mc[0] = mn[0]; mc[1] = mn[1];
    }
    #pragma unroll
    for (int h = 0; h < 2; ++h) {
        lac[h] += __shfl_xor_sync(0xFFFFFFFFu, lac[h], 1);
        lac[h] += __shfl_xor_sync(0xFFFFFFFFu, lac[h], 2);
    }
    const float inv0 = 1.0f / lac[0], inv1 = 1.0f / lac[1];
    const int r0 = iw + rq, r1 = r0 + 8;
    #pragma unroll
    for (int np = 0; np < 4; ++np)
        #pragma unroll
        for (int n8 = 0; n8 < 2; ++n8) {
            const int c = ni*64 + np*16 + n8*8 + cq*2;
            const float bb0 = bo[c], bb1 = bo[c + 1];
            const float* a = acc[np][n8];
            float z00 = fmaxf(a[0]*inv0 + bb0, 0.0f);
            float z01 = fmaxf(a[1]*inv0 + bb1, 0.0f);
            float z10 = fmaxf(a[2]*inv1 + bb0, 0.0f);
            float z11 = fmaxf(a[3]*inv1 + bb1, 0.0f);
            *(float2*)&out[((size_t)b*NN + r0)*NO + c] = make_float2(z00, z01);
            *(float2*)&out[((size_t)b*NN + r1)*NO + c] = make_float2(z10, z11);
        }
}

// ---------------------------------------------------------------------------
extern "C" void kernel_launch(void* const* d_in, const int* in_sizes, int n_in,
                              void* d_out, int out_size) {
    const float* x   = (const float*)d_in[0];
    const int*   adj = (const int*)  d_in[1];
    const float* Wh  = (const float*)d_in[2];
    const float* ah  = (const float*)d_in[3];
    const float* bh  = (const float*)d_in[4];
    const float* Wo  = (const float*)d_in[5];
    const float* ao  = (const float*)d_in[6];
    const float* bo  = (const float*)d_in[7];
    float* out = (float*)d_out;

    const int smem_gemm = (64 + 64 + 128 + 128) * 72 * 2;   // 55296 (>= transpose/partials)
    const int smem1 = 64*72*2 + 64*8;      // 9728
    const int smem2 = 128*72*2 + 64*8;     // 18944
    cudaFuncSetAttribute(gemm1_fused_kernel, cudaFuncAttributeMaxDynamicSharedMemorySize, smem_gemm);
    cudaFuncSetAttribute(gemm2_fused_kernel, cudaFuncAttributeMaxDynamicSharedMemorySize, smem_gemm);
    cudaFuncSetAttribute(agg1_mma_kernel, cudaFuncAttributeMaxDynamicSharedMemorySize, smem1);
    cudaFuncSetAttribute(agg2_mma_kernel, cudaFuncAttributeMaxDynamicSharedMemorySize, smem2);

    pack_adj_kernel<<<(BB*NN)/8, 256>>>(adj);
    split_x_kernel<<<(BB*NN*NF/2)/256, 256>>>(x);
    transWh_kernel<<<C1, 128>>>(Wh);
    transWo_kernel<<<NO, 256>>>(Wo);

    gemm1_fused_kernel<<<dim3(C1/128, (BB*NN)/64), 256, smem_gemm>>>(ah);
    agg1_mma_kernel<<<dim3(NH, NN / 128, BB), 256, smem1>>>(bh);

    gemm2_fused_kernel<<<dim3(NO/128, (BB*NN)/64), 256, smem_gemm>>>(ao);
    agg2_mma_kernel<<<dim3(NN / 32, BB), 128, smem2>>>(bo, out);
}